// round 14
// baseline (speedup 1.0000x reference)
#include <cuda_runtime.h>
#include <cuda_fp16.h>
#include <math.h>

#define N_NODES 50000
#define N_EDGES 1600000
#define D 128
#define BN_EPS 1e-5f
#define NB 196   // scan blocks: 196*256 = 50176 >= N_NODES

// ---------------- device scratch (no allocations allowed) ----------------
__device__ __align__(16) float  g_hws[N_NODES * D];   // (h @ W) * dinv[row], fp32
__device__ __align__(16) __half g_hws_h[N_NODES * D]; // same, fp16 (gather copy)
__device__ __align__(16) float  g_agg[N_NODES * D];   // pre-BN activations
__device__ int   g_src[N_EDGES];
__device__ int   g_dst[N_EDGES];
__device__ int   g_is_i32 = 0;                        // set-only dtype flag
__device__ int   g_deg[N_NODES];
__device__ int   g_rowstart[N_NODES + 1];
__device__ int   g_cursor[N_NODES];
__device__ int   g_csr_src[N_EDGES];
__device__ int   g_blocksum[NB];
__device__ int   g_blockoff[NB];
__device__ float g_dinv[N_NODES];                     // rsqrt(deg+2)
__device__ float g_colsum[D];
__device__ float g_colsq[D];
__device__ float g_scale[D];
__device__ float g_shift[D];

// ---------------- tf32 helpers (fragment layout verified R6/R11) -----------
__device__ __forceinline__ unsigned f2tf32(float x) {
    unsigned r;
    asm("cvt.rna.tf32.f32 %0, %1;" : "=r"(r) : "f"(x));
    return r;
}
__device__ __forceinline__ void mma_tf32(float c[4], const unsigned a[4],
                                         unsigned b0, unsigned b1) {
    asm("mma.sync.aligned.m16n8k8.row.col.f32.tf32.tf32.f32 "
        "{%0,%1,%2,%3}, {%4,%5,%6,%7}, {%8,%9}, {%0,%1,%2,%3};"
        : "+f"(c[0]), "+f"(c[1]), "+f"(c[2]), "+f"(c[3])
        : "r"(a[0]), "r"(a[1]), "r"(a[2]), "r"(a[3]), "r"(b0), "r"(b1));
}

// ---------------- input canonicalization + degree zero ----------------
__global__ void detect_kernel(const int* __restrict__ p32) {
    int i = blockIdx.x * blockDim.x + threadIdx.x;
    if (i < N_NODES) g_deg[i] = 0;
    if (i < 8192 && p32[2 * i + 1] != 0) g_is_i32 = 1;
}

__global__ void convert_count_kernel(const void* __restrict__ eiv) {
    int e = blockIdx.x * blockDim.x + threadIdx.x;
    if (e >= N_EDGES) return;
    int s, d;
    if (g_is_i32) {
        const int* p = (const int*)eiv;
        s = p[e]; d = p[N_EDGES + e];
    } else {
        const long long* p = (const long long*)eiv;
        s = (int)p[e]; d = (int)p[N_EDGES + e];
    }
    g_src[e] = s;
    g_dst[e] = d;
    atomicAdd(&g_deg[d], 1);
}

// ---- grid scan ----
__global__ void scanA_kernel() {
    __shared__ int wsum[8];
    const int tid = threadIdx.x, lane = tid & 31, w = tid >> 5;
    const int i = blockIdx.x * 256 + tid;
    int v = (i < N_NODES) ? g_deg[i] : 0;
    int x = v;
#pragma unroll
    for (int off = 1; off < 32; off <<= 1) {
        int n = __shfl_up_sync(0xffffffffu, x, off);
        if (lane >= off) x += n;
    }
    if (lane == 31) wsum[w] = x;
    __syncthreads();
    if (w == 0) {
        int t = (lane < 8) ? wsum[lane] : 0;
#pragma unroll
        for (int off = 1; off < 8; off <<= 1) {
            int n = __shfl_up_sync(0xffffffffu, t, off);
            if (lane >= off) t += n;
        }
        if (lane < 8) wsum[lane] = t;
    }
    __syncthreads();
    int wpre = (w == 0) ? 0 : wsum[w - 1];
    if (i < N_NODES) {
        g_rowstart[i] = x - v + wpre;
        g_dinv[i] = rsqrtf((float)v + 2.0f);
    }
    if (tid == 255) g_blocksum[blockIdx.x] = x + wpre;
}

__global__ void scanB_kernel() {
    __shared__ int wsum[8];
    const int tid = threadIdx.x, lane = tid & 31, w = tid >> 5;
    int v = (tid < NB) ? g_blocksum[tid] : 0;
    int x = v;
#pragma unroll
    for (int off = 1; off < 32; off <<= 1) {
        int n = __shfl_up_sync(0xffffffffu, x, off);
        if (lane >= off) x += n;
    }
    if (lane == 31) wsum[w] = x;
    __syncthreads();
    if (w == 0) {
        int t = (lane < 8) ? wsum[lane] : 0;
#pragma unroll
        for (int off = 1; off < 8; off <<= 1) {
            int n = __shfl_up_sync(0xffffffffu, t, off);
            if (lane >= off) t += n;
        }
        if (lane < 8) wsum[lane] = t;
    }
    __syncthreads();
    int wpre = (w == 0) ? 0 : wsum[w - 1];
    if (tid < NB) g_blockoff[tid] = x - v + wpre;
    if (tid == 255) g_rowstart[N_NODES] = x + wpre;
}

__global__ void scanC_kernel() {
    int i = blockIdx.x * 256 + threadIdx.x;
    if (i < N_NODES) {
        int rs = g_rowstart[i] + g_blockoff[blockIdx.x];
        g_rowstart[i] = rs;
        g_cursor[i] = rs;
    }
}

__global__ void fill_kernel() {
    int e = blockIdx.x * blockDim.x + threadIdx.x;
    if (e < N_EDGES) {
        int p = atomicAdd(&g_cursor[g_dst[e]], 1);
        g_csr_src[p] = g_src[e];
    }
}

// ---------------- split-tf32 tensor GEMM, double-buffered (R12 champion) ----
__global__ void __launch_bounds__(256) gemm_kernel(const float* __restrict__ A,
                                                   const float* __restrict__ W,
                                                   int mode) {
    __shared__ float sAh[2][64][20], sAl[2][64][20];    // row-major, pad 20
    __shared__ float sWh[2][16][136], sWl[2][16][136];  // k-major, pad 136
    __shared__ float s_scale[D], s_shift[D];

    const int tid = threadIdx.x;
    const int rb = blockIdx.x * 64;
    const int lane = tid & 31, w = tid >> 5;
    const int rg = w & 3, cg = w >> 2;
    const int gi = lane >> 2, t4 = lane & 3;

    if (mode && tid < D) { s_scale[tid] = g_scale[tid]; s_shift[tid] = g_shift[tid]; }
    if (blockIdx.x == 0 && tid < D) { g_colsum[tid] = 0.0f; g_colsq[tid] = 0.0f; }
    __syncthreads();

    float c[8][4];
#pragma unroll
    for (int n0 = 0; n0 < 8; n0++)
#pragma unroll
        for (int j = 0; j < 4; j++) c[n0][j] = 0.0f;

    const int a_row = tid >> 2;
    const int a_kp = (tid & 3) * 4;
    const int grow = rb + a_row;
    const int wk0 = tid >> 5;
    const int wk1 = 8 + wk0;
    const int wc4 = (tid & 31) * 4;
    const float* __restrict__ srcA = mode ? g_agg : A;

    float4 aReg, wReg0, wReg1;

    auto loadA = [&](int kk) {
        float4 a = make_float4(0.f, 0.f, 0.f, 0.f);
        if (grow < N_NODES) {
            a = *(const float4*)&srcA[grow * D + kk + a_kp];
            if (mode) {
                int cb = kk + a_kp;
                a.x = fmaxf(a.x * s_scale[cb + 0] + s_shift[cb + 0], 0.f);
                a.y = fmaxf(a.y * s_scale[cb + 1] + s_shift[cb + 1], 0.f);
                a.z = fmaxf(a.z * s_scale[cb + 2] + s_shift[cb + 2], 0.f);
                a.w = fmaxf(a.w * s_scale[cb + 3] + s_shift[cb + 3], 0.f);
            }
        }
        return a;
    };
    auto storeA = [&](int buf, float4 a) {
        float hx = __uint_as_float(f2tf32(a.x));
        float hy = __uint_as_float(f2tf32(a.y));
        float hz = __uint_as_float(f2tf32(a.z));
        float hw = __uint_as_float(f2tf32(a.w));
        *(float4*)&sAh[buf][a_row][a_kp] = make_float4(hx, hy, hz, hw);
        *(float4*)&sAl[buf][a_row][a_kp] = make_float4(
            __uint_as_float(f2tf32(a.x - hx)), __uint_as_float(f2tf32(a.y - hy)),
            __uint_as_float(f2tf32(a.z - hz)), __uint_as_float(f2tf32(a.w - hw)));
    };
    auto storeW = [&](int buf, int k, float4 b) {
        float hx = __uint_as_float(f2tf32(b.x));
        float hy = __uint_as_float(f2tf32(b.y));
        float hz = __uint_as_float(f2tf32(b.z));
        float hw = __uint_as_float(f2tf32(b.w));
        *(float4*)&sWh[buf][k][wc4] = make_float4(hx, hy, hz, hw);
        *(float4*)&sWl[buf][k][wc4] = make_float4(
            __uint_as_float(f2tf32(b.x - hx)), __uint_as_float(f2tf32(b.y - hy)),
            __uint_as_float(f2tf32(b.z - hz)), __uint_as_float(f2tf32(b.w - hw)));
    };

    aReg  = loadA(0);
    wReg0 = *(const float4*)&W[wk0 * D + wc4];
    wReg1 = *(const float4*)&W[wk1 * D + wc4];
    storeA(0, aReg);
    storeW(0, wk0, wReg0);
    storeW(0, wk1, wReg1);
    __syncthreads();

    for (int s = 0; s < 8; s++) {
        const int cur = s & 1;
        const int kk_next = (s + 1) * 16;

        if (s < 7) {
            aReg  = loadA(kk_next);
            wReg0 = *(const float4*)&W[(kk_next + wk0) * D + wc4];
            wReg1 = *(const float4*)&W[(kk_next + wk1) * D + wc4];
        }

#pragma unroll
        for (int ks = 0; ks < 2; ks++) {
            const int k0 = ks * 8;
            const int r0 = rg * 16 + gi, r1 = r0 + 8;
            unsigned ah[4] = {__float_as_uint(sAh[cur][r0][k0 + t4]),
                              __float_as_uint(sAh[cur][r1][k0 + t4]),
                              __float_as_uint(sAh[cur][r0][k0 + t4 + 4]),
                              __float_as_uint(sAh[cur][r1][k0 + t4 + 4])};
            unsigned al[4] = {__float_as_uint(sAl[cur][r0][k0 + t4]),
                              __float_as_uint(sAl[cur][r1][k0 + t4]),
                              __float_as_uint(sAl[cur][r0][k0 + t4 + 4]),
                              __float_as_uint(sAl[cur][r1][k0 + t4 + 4])};
#pragma unroll
            for (int n0 = 0; n0 < 8; n0++) {
                int nb = cg * 64 + n0 * 8 + gi;
                unsigned b0h = __float_as_uint(sWh[cur][k0 + t4][nb]);
                unsigned b1h = __float_as_uint(sWh[cur][k0 + t4 + 4][nb]);
                unsigned b0l = __float_as_uint(sWl[cur][k0 + t4][nb]);
                unsigned b1l = __float_as_uint(sWl[cur][k0 + t4 + 4][nb]);
                mma_tf32(c[n0], ah, b0h, b1h);   // hi*hi
                mma_tf32(c[n0], ah, b0l, b1l);   // hi*lo
                mma_tf32(c[n0], al, b0h, b1h);   // lo*hi
            }
        }

        if (s < 7) {
            const int nxt = cur ^ 1;
            storeA(nxt, aReg);
            storeW(nxt, wk0, wReg0);
            storeW(nxt, wk1, wReg1);
            __syncthreads();
        }
    }

    const int row0 = rb + rg * 16 + gi;
    const int row1 = row0 + 8;
    const float di0 = (row0 < N_NODES) ? g_dinv[row0] : 0.0f;
    const float di1 = (row1 < N_NODES) ? g_dinv[row1] : 0.0f;
    __half2* hout = reinterpret_cast<__half2*>(g_hws_h);
#pragma unroll
    for (int n0 = 0; n0 < 8; n0++) {
        int n = cg * 64 + n0 * 8 + 2 * t4;
        int hc = n >> 1;
        if (row0 < N_NODES) {
            float2 v = make_float2(c[n0][0] * di0, c[n0][1] * di0);
            *(float2*)&g_hws[row0 * D + n] = v;
            hout[row0 * (D / 2) + hc] = __floats2half2_rn(v.x, v.y);
        }
        if (row1 < N_NODES) {
            float2 v = make_float2(c[n0][2] * di1, c[n0][3] * di1);
            *(float2*)&g_hws[row1 * D + n] = v;
            hout[row1 * (D / 2) + hc] = __floats2half2_rn(v.x, v.y);
        }
    }
}

// ---------------- aggregate + fused BN stats ---------------------------------
// Warp processes 8 consecutive nodes; per-lane register accumulation of column
// sum/sumsq; 8 atomicAdds per lane at warp end. No block barrier, no smem.
__global__ void aggregate_kernel(const float* __restrict__ b) {
    const int wid = blockIdx.x * 8 + (threadIdx.x >> 5);
    const int lane = threadIdx.x & 31;
    const int nbase = wid * 8;
    if (nbase >= N_NODES) return;

    const uint2* __restrict__ hh = reinterpret_cast<const uint2*>(g_hws_h);
    const float4* __restrict__ hws4 = reinterpret_cast<const float4*>(g_hws);
    const float4 b4 = reinterpret_cast<const float4*>(b)[lane];

    float4 csum = make_float4(0.f, 0.f, 0.f, 0.f);
    float4 csq  = make_float4(0.f, 0.f, 0.f, 0.f);

#pragma unroll 1
    for (int it = 0; it < 8; it++) {
        const int node = nbase + it;
        if (node >= N_NODES) break;
        const int beg = g_rowstart[node];
        const int end = g_rowstart[node + 1];

        float4 acc = make_float4(0.f, 0.f, 0.f, 0.f);
        for (int k0 = beg; k0 < end; k0 += 32) {
            int t = k0 + lane;
            int idx = (t < end) ? g_csr_src[t] : 0;
            int m = min(32, end - k0);
#pragma unroll 8
            for (int j = 0; j < m; j++) {
                int s = __shfl_sync(0xffffffffu, idx, j);
                uint2 raw = hh[s * 32 + lane];
                float2 f0 = __half22float2(*reinterpret_cast<__half2*>(&raw.x));
                float2 f1 = __half22float2(*reinterpret_cast<__half2*>(&raw.y));
                acc.x += f0.x; acc.y += f0.y; acc.z += f1.x; acc.w += f1.y;
            }
        }

        float4 self = hws4[node * 32 + lane];
        float dinv = g_dinv[node];
        float4 o;
        o.x = dinv * (acc.x + 2.0f * self.x) + b4.x;
        o.y = dinv * (acc.y + 2.0f * self.y) + b4.y;
        o.z = dinv * (acc.z + 2.0f * self.z) + b4.z;
        o.w = dinv * (acc.w + 2.0f * self.w) + b4.w;
        reinterpret_cast<float4*>(g_agg)[node * 32 + lane] = o;

        csum.x += o.x; csum.y += o.y; csum.z += o.z; csum.w += o.w;
        csq.x += o.x * o.x; csq.y += o.y * o.y;
        csq.z += o.z * o.z; csq.w += o.w * o.w;
    }

    const int c = 4 * lane;
    atomicAdd(&g_colsum[c + 0], csum.x); atomicAdd(&g_colsum[c + 1], csum.y);
    atomicAdd(&g_colsum[c + 2], csum.z); atomicAdd(&g_colsum[c + 3], csum.w);
    atomicAdd(&g_colsq[c + 0], csq.x);   atomicAdd(&g_colsq[c + 1], csq.y);
    atomicAdd(&g_colsq[c + 2], csq.z);   atomicAdd(&g_colsq[c + 3], csq.w);
}

__global__ void bn_final_kernel(const float* __restrict__ gamma,
                                const float* __restrict__ beta) {
    int c = threadIdx.x;
    float mean = g_colsum[c] * (1.0f / (float)N_NODES);
    float var = g_colsq[c] * (1.0f / (float)N_NODES) - mean * mean;
    float sc = gamma[c] * rsqrtf(var + BN_EPS);
    g_scale[c] = sc;
    g_shift[c] = beta[c] - mean * sc;
}

// final layer only: out = relu(agg*scale + shift)
__global__ void apply_kernel(float* __restrict__ out) {
    int idx = blockIdx.x * blockDim.x + threadIdx.x;
    if (idx >= N_NODES * D) return;
    int c = idx & (D - 1);
    float v = g_agg[idx] * g_scale[c] + g_shift[c];
    out[idx] = fmaxf(v, 0.0f);
}

// ---------------- launch ----------------
extern "C" void kernel_launch(void* const* d_in, const int* in_sizes, int n_in,
                              void* d_out, int out_size) {
    const float* x = (const float*)d_in[0];
    const void* ei = d_in[1];
    const float* W[3]  = {(const float*)d_in[2],  (const float*)d_in[6],  (const float*)d_in[10]};
    const float* bb[3] = {(const float*)d_in[3],  (const float*)d_in[7],  (const float*)d_in[11]};
    const float* gg[3] = {(const float*)d_in[4],  (const float*)d_in[8],  (const float*)d_in[12]};
    const float* be[3] = {(const float*)d_in[5],  (const float*)d_in[9],  (const float*)d_in[13]};
    float* out = (float*)d_out;

    const int eblocks = (N_EDGES + 255) / 256;
    const int gemm_blocks = (N_NODES + 63) / 64;
    const int agg_blocks = (N_NODES + 63) / 64;     // 8 warps x 8 nodes / block
    const int app_blocks = (N_NODES * D + 255) / 256;

    detect_kernel<<<NB, 256>>>((const int*)ei);                 // 1
    convert_count_kernel<<<eblocks, 256>>>(ei);                 // 2
    scanA_kernel<<<NB, 256>>>();                                // 3 (writes dinv)
    gemm_kernel<<<gemm_blocks, 256>>>(x, W[0], 0);              // 4 <- ncu slot
    scanB_kernel<<<1, 256>>>();                                 // 5
    scanC_kernel<<<NB, 256>>>();                                // 6
    fill_kernel<<<eblocks, 256>>>();                            // 7

    for (int layer = 0; layer < 3; layer++) {
        if (layer > 0)
            gemm_kernel<<<gemm_blocks, 256>>>(x, W[layer], 1);
        aggregate_kernel<<<agg_blocks, 256>>>(bb[layer]);
        bn_final_kernel<<<1, D>>>(gg[layer], be[layer]);
    }
    apply_kernel<<<app_blocks, 256>>>(out);
}

// round 15
// speedup vs baseline: 3.2416x; 3.2416x over previous
#include <cuda_runtime.h>
#include <cuda_fp16.h>
#include <math.h>

#define N_NODES 50000
#define N_EDGES 1600000
#define D 128
#define BN_EPS 1e-5f
#define NB 196   // scan blocks: 196*256 = 50176 >= N_NODES

// ---------------- device scratch (no allocations allowed) ----------------
__device__ __align__(16) __half g_hws_h[N_NODES * D]; // (h @ W) * dinv[row], fp16
__device__ __align__(16) float  g_agg[N_NODES * D];   // pre-BN activations
__device__ int   g_src[N_EDGES];
__device__ int   g_dst[N_EDGES];
__device__ int   g_is_i32 = 0;                        // set-only dtype flag
__device__ int   g_deg[N_NODES];
__device__ int   g_rowstart[N_NODES + 1];
__device__ int   g_cursor[N_NODES];
__device__ int   g_csr_src[N_EDGES];
__device__ int   g_blocksum[NB];
__device__ int   g_blockoff[NB];
__device__ float g_dinv[N_NODES];                     // rsqrt(deg+2)
__device__ float g_colsum[D];
__device__ float g_colsq[D];
__device__ float g_scale[D];
__device__ float g_shift[D];

// ---------------- tf32 helpers (fragment layout verified R6/R11) -----------
__device__ __forceinline__ unsigned f2tf32(float x) {
    unsigned r;
    asm("cvt.rna.tf32.f32 %0, %1;" : "=r"(r) : "f"(x));
    return r;
}
__device__ __forceinline__ void mma_tf32(float c[4], const unsigned a[4],
                                         unsigned b0, unsigned b1) {
    asm("mma.sync.aligned.m16n8k8.row.col.f32.tf32.tf32.f32 "
        "{%0,%1,%2,%3}, {%4,%5,%6,%7}, {%8,%9}, {%0,%1,%2,%3};"
        : "+f"(c[0]), "+f"(c[1]), "+f"(c[2]), "+f"(c[3])
        : "r"(a[0]), "r"(a[1]), "r"(a[2]), "r"(a[3]), "r"(b0), "r"(b1));
}

// ---------------- input canonicalization + degree zero ----------------
__global__ void detect_kernel(const int* __restrict__ p32) {
    int i = blockIdx.x * blockDim.x + threadIdx.x;
    if (i < N_NODES) g_deg[i] = 0;
    if (i < 8192 && p32[2 * i + 1] != 0) g_is_i32 = 1;
}

__global__ void convert_count_kernel(const void* __restrict__ eiv) {
    int e = blockIdx.x * blockDim.x + threadIdx.x;
    if (e >= N_EDGES) return;
    int s, d;
    if (g_is_i32) {
        const int* p = (const int*)eiv;
        s = p[e]; d = p[N_EDGES + e];
    } else {
        const long long* p = (const long long*)eiv;
        s = (int)p[e]; d = (int)p[N_EDGES + e];
    }
    g_src[e] = s;
    g_dst[e] = d;
    atomicAdd(&g_deg[d], 1);
}

// ---- grid scan ----
__global__ void scanA_kernel() {
    __shared__ int wsum[8];
    const int tid = threadIdx.x, lane = tid & 31, w = tid >> 5;
    const int i = blockIdx.x * 256 + tid;
    int v = (i < N_NODES) ? g_deg[i] : 0;
    int x = v;
#pragma unroll
    for (int off = 1; off < 32; off <<= 1) {
        int n = __shfl_up_sync(0xffffffffu, x, off);
        if (lane >= off) x += n;
    }
    if (lane == 31) wsum[w] = x;
    __syncthreads();
    if (w == 0) {
        int t = (lane < 8) ? wsum[lane] : 0;
#pragma unroll
        for (int off = 1; off < 8; off <<= 1) {
            int n = __shfl_up_sync(0xffffffffu, t, off);
            if (lane >= off) t += n;
        }
        if (lane < 8) wsum[lane] = t;
    }
    __syncthreads();
    int wpre = (w == 0) ? 0 : wsum[w - 1];
    if (i < N_NODES) {
        g_rowstart[i] = x - v + wpre;
        g_dinv[i] = rsqrtf((float)v + 2.0f);
    }
    if (tid == 255) g_blocksum[blockIdx.x] = x + wpre;
}

__global__ void scanB_kernel() {
    __shared__ int wsum[8];
    const int tid = threadIdx.x, lane = tid & 31, w = tid >> 5;
    int v = (tid < NB) ? g_blocksum[tid] : 0;
    int x = v;
#pragma unroll
    for (int off = 1; off < 32; off <<= 1) {
        int n = __shfl_up_sync(0xffffffffu, x, off);
        if (lane >= off) x += n;
    }
    if (lane == 31) wsum[w] = x;
    __syncthreads();
    if (w == 0) {
        int t = (lane < 8) ? wsum[lane] : 0;
#pragma unroll
        for (int off = 1; off < 8; off <<= 1) {
            int n = __shfl_up_sync(0xffffffffu, t, off);
            if (lane >= off) t += n;
        }
        if (lane < 8) wsum[lane] = t;
    }
    __syncthreads();
    int wpre = (w == 0) ? 0 : wsum[w - 1];
    if (tid < NB) g_blockoff[tid] = x - v + wpre;
    if (tid == 255) g_rowstart[N_NODES] = x + wpre;
}

__global__ void scanC_kernel() {
    int i = blockIdx.x * 256 + threadIdx.x;
    if (i < N_NODES) {
        int rs = g_rowstart[i] + g_blockoff[blockIdx.x];
        g_rowstart[i] = rs;
        g_cursor[i] = rs;
    }
}

__global__ void fill_kernel() {
    int e = blockIdx.x * blockDim.x + threadIdx.x;
    if (e < N_EDGES) {
        int p = atomicAdd(&g_cursor[g_dst[e]], 1);
        g_csr_src[p] = g_src[e];
    }
}

// ---------------- split-tf32 tensor GEMM, double-buffered (R12 champion) ----
// Epilogue writes fp16 only (g_hws fp32 eliminated; self term read fp16).
__global__ void __launch_bounds__(256) gemm_kernel(const float* __restrict__ A,
                                                   const float* __restrict__ W,
                                                   int mode) {
    __shared__ float sAh[2][64][20], sAl[2][64][20];    // row-major, pad 20
    __shared__ float sWh[2][16][136], sWl[2][16][136];  // k-major, pad 136
    __shared__ float s_scale[D], s_shift[D];

    const int tid = threadIdx.x;
    const int rb = blockIdx.x * 64;
    const int lane = tid & 31, w = tid >> 5;
    const int rg = w & 3, cg = w >> 2;
    const int gi = lane >> 2, t4 = lane & 3;

    if (mode && tid < D) { s_scale[tid] = g_scale[tid]; s_shift[tid] = g_shift[tid]; }
    if (blockIdx.x == 0 && tid < D) { g_colsum[tid] = 0.0f; g_colsq[tid] = 0.0f; }
    __syncthreads();

    float c[8][4];
#pragma unroll
    for (int n0 = 0; n0 < 8; n0++)
#pragma unroll
        for (int j = 0; j < 4; j++) c[n0][j] = 0.0f;

    const int a_row = tid >> 2;
    const int a_kp = (tid & 3) * 4;
    const int grow = rb + a_row;
    const int wk0 = tid >> 5;
    const int wk1 = 8 + wk0;
    const int wc4 = (tid & 31) * 4;
    const float* __restrict__ srcA = mode ? g_agg : A;

    float4 aReg, wReg0, wReg1;

    auto loadA = [&](int kk) {
        float4 a = make_float4(0.f, 0.f, 0.f, 0.f);
        if (grow < N_NODES) {
            a = *(const float4*)&srcA[grow * D + kk + a_kp];
            if (mode) {
                int cb = kk + a_kp;
                a.x = fmaxf(a.x * s_scale[cb + 0] + s_shift[cb + 0], 0.f);
                a.y = fmaxf(a.y * s_scale[cb + 1] + s_shift[cb + 1], 0.f);
                a.z = fmaxf(a.z * s_scale[cb + 2] + s_shift[cb + 2], 0.f);
                a.w = fmaxf(a.w * s_scale[cb + 3] + s_shift[cb + 3], 0.f);
            }
        }
        return a;
    };
    auto storeA = [&](int buf, float4 a) {
        float hx = __uint_as_float(f2tf32(a.x));
        float hy = __uint_as_float(f2tf32(a.y));
        float hz = __uint_as_float(f2tf32(a.z));
        float hw = __uint_as_float(f2tf32(a.w));
        *(float4*)&sAh[buf][a_row][a_kp] = make_float4(hx, hy, hz, hw);
        *(float4*)&sAl[buf][a_row][a_kp] = make_float4(
            __uint_as_float(f2tf32(a.x - hx)), __uint_as_float(f2tf32(a.y - hy)),
            __uint_as_float(f2tf32(a.z - hz)), __uint_as_float(f2tf32(a.w - hw)));
    };
    auto storeW = [&](int buf, int k, float4 b) {
        float hx = __uint_as_float(f2tf32(b.x));
        float hy = __uint_as_float(f2tf32(b.y));
        float hz = __uint_as_float(f2tf32(b.z));
        float hw = __uint_as_float(f2tf32(b.w));
        *(float4*)&sWh[buf][k][wc4] = make_float4(hx, hy, hz, hw);
        *(float4*)&sWl[buf][k][wc4] = make_float4(
            __uint_as_float(f2tf32(b.x - hx)), __uint_as_float(f2tf32(b.y - hy)),
            __uint_as_float(f2tf32(b.z - hz)), __uint_as_float(f2tf32(b.w - hw)));
    };

    aReg  = loadA(0);
    wReg0 = *(const float4*)&W[wk0 * D + wc4];
    wReg1 = *(const float4*)&W[wk1 * D + wc4];
    storeA(0, aReg);
    storeW(0, wk0, wReg0);
    storeW(0, wk1, wReg1);
    __syncthreads();

    for (int s = 0; s < 8; s++) {
        const int cur = s & 1;
        const int kk_next = (s + 1) * 16;

        if (s < 7) {
            aReg  = loadA(kk_next);
            wReg0 = *(const float4*)&W[(kk_next + wk0) * D + wc4];
            wReg1 = *(const float4*)&W[(kk_next + wk1) * D + wc4];
        }

#pragma unroll
        for (int ks = 0; ks < 2; ks++) {
            const int k0 = ks * 8;
            const int r0 = rg * 16 + gi, r1 = r0 + 8;
            unsigned ah[4] = {__float_as_uint(sAh[cur][r0][k0 + t4]),
                              __float_as_uint(sAh[cur][r1][k0 + t4]),
                              __float_as_uint(sAh[cur][r0][k0 + t4 + 4]),
                              __float_as_uint(sAh[cur][r1][k0 + t4 + 4])};
            unsigned al[4] = {__float_as_uint(sAl[cur][r0][k0 + t4]),
                              __float_as_uint(sAl[cur][r1][k0 + t4]),
                              __float_as_uint(sAl[cur][r0][k0 + t4 + 4]),
                              __float_as_uint(sAl[cur][r1][k0 + t4 + 4])};
#pragma unroll
            for (int n0 = 0; n0 < 8; n0++) {
                int nb = cg * 64 + n0 * 8 + gi;
                unsigned b0h = __float_as_uint(sWh[cur][k0 + t4][nb]);
                unsigned b1h = __float_as_uint(sWh[cur][k0 + t4 + 4][nb]);
                unsigned b0l = __float_as_uint(sWl[cur][k0 + t4][nb]);
                unsigned b1l = __float_as_uint(sWl[cur][k0 + t4 + 4][nb]);
                mma_tf32(c[n0], ah, b0h, b1h);   // hi*hi
                mma_tf32(c[n0], ah, b0l, b1l);   // hi*lo
                mma_tf32(c[n0], al, b0h, b1h);   // lo*hi
            }
        }

        if (s < 7) {
            const int nxt = cur ^ 1;
            storeA(nxt, aReg);
            storeW(nxt, wk0, wReg0);
            storeW(nxt, wk1, wReg1);
            __syncthreads();
        }
    }

    // ---- epilogue: fp16 only ----
    const int row0 = rb + rg * 16 + gi;
    const int row1 = row0 + 8;
    const float di0 = (row0 < N_NODES) ? g_dinv[row0] : 0.0f;
    const float di1 = (row1 < N_NODES) ? g_dinv[row1] : 0.0f;
    __half2* hout = reinterpret_cast<__half2*>(g_hws_h);
#pragma unroll
    for (int n0 = 0; n0 < 8; n0++) {
        int n = cg * 64 + n0 * 8 + 2 * t4;
        int hc = n >> 1;
        if (row0 < N_NODES)
            hout[row0 * (D / 2) + hc] = __floats2half2_rn(c[n0][0] * di0, c[n0][1] * di0);
        if (row1 < N_NODES)
            hout[row1 * (D / 2) + hc] = __floats2half2_rn(c[n0][2] * di1, c[n0][3] * di1);
    }
}

// ---------------- aggregate (warp per node, fp16 gathers; R12 structure) ----
__global__ void aggregate_kernel(const float* __restrict__ b) {
    const int node = blockIdx.x * 8 + (threadIdx.x >> 5);
    const int lane = threadIdx.x & 31;
    if (node >= N_NODES) return;

    const int beg = g_rowstart[node];
    const int end = g_rowstart[node + 1];
    const uint2* __restrict__ hh = reinterpret_cast<const uint2*>(g_hws_h);

    float4 acc = make_float4(0.0f, 0.0f, 0.0f, 0.0f);
    for (int k0 = beg; k0 < end; k0 += 32) {
        int t = k0 + lane;
        int idx = (t < end) ? g_csr_src[t] : 0;
        int m = min(32, end - k0);
#pragma unroll 8
        for (int j = 0; j < m; j++) {
            int s = __shfl_sync(0xffffffffu, idx, j);
            uint2 raw = hh[s * 32 + lane];
            float2 f0 = __half22float2(*reinterpret_cast<__half2*>(&raw.x));
            float2 f1 = __half22float2(*reinterpret_cast<__half2*>(&raw.y));
            acc.x += f0.x; acc.y += f0.y; acc.z += f1.x; acc.w += f1.y;
        }
    }

    // self term from fp16 copy
    uint2 sraw = hh[node * 32 + lane];
    float2 s0 = __half22float2(*reinterpret_cast<__half2*>(&sraw.x));
    float2 s1 = __half22float2(*reinterpret_cast<__half2*>(&sraw.y));
    float dinv = g_dinv[node];
    float4 b4 = reinterpret_cast<const float4*>(b)[lane];
    float4 o;
    o.x = dinv * (acc.x + 2.0f * s0.x) + b4.x;
    o.y = dinv * (acc.y + 2.0f * s0.y) + b4.y;
    o.z = dinv * (acc.z + 2.0f * s1.x) + b4.z;
    o.w = dinv * (acc.w + 2.0f * s1.y) + b4.w;
    reinterpret_cast<float4*>(g_agg)[node * 32 + lane] = o;
}

// column sums/sumsq over g_agg; block handles 128 rows (thread = column)
__global__ void stats_kernel() {
    const int c = threadIdx.x;
    const int r0 = blockIdx.x * 128;
    float s = 0.0f, sq = 0.0f;
    for (int i = 0; i < 128; i++) {
        int r = r0 + i;
        if (r >= N_NODES) break;
        float v = g_agg[r * D + c];
        s += v;
        sq += v * v;
    }
    atomicAdd(&g_colsum[c], s);
    atomicAdd(&g_colsq[c], sq);
}

__global__ void bn_final_kernel(const float* __restrict__ gamma,
                                const float* __restrict__ beta) {
    int c = threadIdx.x;
    float mean = g_colsum[c] * (1.0f / (float)N_NODES);
    float var = g_colsq[c] * (1.0f / (float)N_NODES) - mean * mean;
    float sc = gamma[c] * rsqrtf(var + BN_EPS);
    g_scale[c] = sc;
    g_shift[c] = beta[c] - mean * sc;
}

// final layer only: out = relu(agg*scale + shift)
__global__ void apply_kernel(float* __restrict__ out) {
    int idx = blockIdx.x * blockDim.x + threadIdx.x;
    if (idx >= N_NODES * D) return;
    int c = idx & (D - 1);
    float v = g_agg[idx] * g_scale[c] + g_shift[c];
    out[idx] = fmaxf(v, 0.0f);
}

// ---------------- launch ----------------
extern "C" void kernel_launch(void* const* d_in, const int* in_sizes, int n_in,
                              void* d_out, int out_size) {
    const float* x = (const float*)d_in[0];
    const void* ei = d_in[1];
    const float* W[3]  = {(const float*)d_in[2],  (const float*)d_in[6],  (const float*)d_in[10]};
    const float* bb[3] = {(const float*)d_in[3],  (const float*)d_in[7],  (const float*)d_in[11]};
    const float* gg[3] = {(const float*)d_in[4],  (const float*)d_in[8],  (const float*)d_in[12]};
    const float* be[3] = {(const float*)d_in[5],  (const float*)d_in[9],  (const float*)d_in[13]};
    float* out = (float*)d_out;

    const int eblocks = (N_EDGES + 255) / 256;
    const int gemm_blocks = (N_NODES + 63) / 64;
    const int agg_blocks = (N_NODES + 7) / 8;
    const int stats_blocks = (N_NODES + 127) / 128;
    const int app_blocks = (N_NODES * D + 255) / 256;

    detect_kernel<<<NB, 256>>>((const int*)ei);                 // 1
    convert_count_kernel<<<eblocks, 256>>>(ei);                 // 2
    scanA_kernel<<<1 * NB, 256>>>();                            // 3 (writes dinv)
    gemm_kernel<<<gemm_blocks, 256>>>(x, W[0], 0);              // 4 <- ncu slot
    scanB_kernel<<<1, 256>>>();                                 // 5
    scanC_kernel<<<NB, 256>>>();                                // 6
    fill_kernel<<<eblocks, 256>>>();                            // 7

    for (int layer = 0; layer < 3; layer++) {
        if (layer > 0)
            gemm_kernel<<<gemm_blocks, 256>>>(x, W[layer], 1);
        aggregate_kernel<<<agg_blocks, 256>>>(bb[layer]);
        stats_kernel<<<stats_blocks, 128>>>();
        bn_final_kernel<<<1, D>>>(gg[layer], be[layer]);
    }
    apply_kernel<<<app_blocks, 256>>>(out);
}

// round 16
// speedup vs baseline: 3.6725x; 1.1329x over previous
#include <cuda_runtime.h>
#include <cuda_fp16.h>
#include <math.h>

#define N_NODES 50000
#define N_EDGES 1600000
#define D 128
#define BN_EPS 1e-5f
#define NB 196   // scan blocks: 196*256 = 50176 >= N_NODES

// ---------------- device scratch (no allocations allowed) ----------------
__device__ __align__(16) __half g_hws_h[N_NODES * D]; // (h @ W) * dinv[row], fp16
__device__ __align__(16) float  g_agg[N_NODES * D];   // pre-BN activations
__device__ int   g_src[N_EDGES];
__device__ int   g_dst[N_EDGES];
__device__ int   g_is_i32 = 0;                        // set-only dtype flag
__device__ int   g_deg[N_NODES];
__device__ int   g_rowstart[N_NODES + 1];
__device__ int   g_cursor[N_NODES];
__device__ int   g_csr_src[N_EDGES];
__device__ int   g_blocksum[NB];
__device__ int   g_blockoff[NB];
__device__ float g_dinv[N_NODES];                     // rsqrt(deg+2)
__device__ float g_colsum[D];
__device__ float g_colsq[D];
__device__ float g_scale[D];
__device__ float g_shift[D];

// ---------------- fp16 split helpers ----------------------------------------
__device__ __forceinline__ unsigned h2u(__half2 h) {
    return *reinterpret_cast<unsigned*>(&h);
}
// mma.m16n8k16 row.col f32.f16.f16.f32 (k16 extension of verified k8 maps)
__device__ __forceinline__ void mma_f16(float c[4], unsigned a0, unsigned a1,
                                        unsigned a2, unsigned a3,
                                        unsigned b0, unsigned b1) {
    asm("mma.sync.aligned.m16n8k16.row.col.f32.f16.f16.f32 "
        "{%0,%1,%2,%3}, {%4,%5,%6,%7}, {%8,%9}, {%0,%1,%2,%3};"
        : "+f"(c[0]), "+f"(c[1]), "+f"(c[2]), "+f"(c[3])
        : "r"(a0), "r"(a1), "r"(a2), "r"(a3), "r"(b0), "r"(b1));
}

// ---------------- input canonicalization + degree zero ----------------
__global__ void detect_kernel(const int* __restrict__ p32) {
    int i = blockIdx.x * blockDim.x + threadIdx.x;
    if (i < N_NODES) g_deg[i] = 0;
    if (i < 8192 && p32[2 * i + 1] != 0) g_is_i32 = 1;
}

__global__ void convert_count_kernel(const void* __restrict__ eiv) {
    int e = blockIdx.x * blockDim.x + threadIdx.x;
    if (e >= N_EDGES) return;
    int s, d;
    if (g_is_i32) {
        const int* p = (const int*)eiv;
        s = p[e]; d = p[N_EDGES + e];
    } else {
        const long long* p = (const long long*)eiv;
        s = (int)p[e]; d = (int)p[N_EDGES + e];
    }
    g_src[e] = s;
    g_dst[e] = d;
    atomicAdd(&g_deg[d], 1);
}

// ---- grid scan ----
__global__ void scanA_kernel() {
    __shared__ int wsum[8];
    const int tid = threadIdx.x, lane = tid & 31, w = tid >> 5;
    const int i = blockIdx.x * 256 + tid;
    int v = (i < N_NODES) ? g_deg[i] : 0;
    int x = v;
#pragma unroll
    for (int off = 1; off < 32; off <<= 1) {
        int n = __shfl_up_sync(0xffffffffu, x, off);
        if (lane >= off) x += n;
    }
    if (lane == 31) wsum[w] = x;
    __syncthreads();
    if (w == 0) {
        int t = (lane < 8) ? wsum[lane] : 0;
#pragma unroll
        for (int off = 1; off < 8; off <<= 1) {
            int n = __shfl_up_sync(0xffffffffu, t, off);
            if (lane >= off) t += n;
        }
        if (lane < 8) wsum[lane] = t;
    }
    __syncthreads();
    int wpre = (w == 0) ? 0 : wsum[w - 1];
    if (i < N_NODES) {
        g_rowstart[i] = x - v + wpre;
        g_dinv[i] = rsqrtf((float)v + 2.0f);
    }
    if (tid == 255) g_blocksum[blockIdx.x] = x + wpre;
}

__global__ void scanB_kernel() {
    __shared__ int wsum[8];
    const int tid = threadIdx.x, lane = tid & 31, w = tid >> 5;
    int v = (tid < NB) ? g_blocksum[tid] : 0;
    int x = v;
#pragma unroll
    for (int off = 1; off < 32; off <<= 1) {
        int n = __shfl_up_sync(0xffffffffu, x, off);
        if (lane >= off) x += n;
    }
    if (lane == 31) wsum[w] = x;
    __syncthreads();
    if (w == 0) {
        int t = (lane < 8) ? wsum[lane] : 0;
#pragma unroll
        for (int off = 1; off < 8; off <<= 1) {
            int n = __shfl_up_sync(0xffffffffu, t, off);
            if (lane >= off) t += n;
        }
        if (lane < 8) wsum[lane] = t;
    }
    __syncthreads();
    int wpre = (w == 0) ? 0 : wsum[w - 1];
    if (tid < NB) g_blockoff[tid] = x - v + wpre;
    if (tid == 255) g_rowstart[N_NODES] = x + wpre;
}

__global__ void scanC_kernel() {
    int i = blockIdx.x * 256 + threadIdx.x;
    if (i < N_NODES) {
        int rs = g_rowstart[i] + g_blockoff[blockIdx.x];
        g_rowstart[i] = rs;
        g_cursor[i] = rs;
    }
}

__global__ void fill_kernel() {
    int e = blockIdx.x * blockDim.x + threadIdx.x;
    if (e < N_EDGES) {
        int p = atomicAdd(&g_cursor[g_dst[e]], 1);
        g_csr_src[p] = g_src[e];
    }
}

// ---------------- split-fp16 tensor GEMM (m16n8k16), double-buffered --------
// Tile 64 rows x 128 cols, 256 threads = 8 warps (rg=w&3 rows, cg=w>>2 cols).
// K sliced 16-deep. hi/lo fp16 split: D = Ah*Wh + Ah*Wl + Al*Wh (lo*lo ~1e-6).
// Smem stores half2 k-pairs. A stride 12 words (gi*12+t4 distinct mod 32);
// W stride 136 words (t4*8+gi distinct mod 32).
__global__ void __launch_bounds__(256) gemm_kernel(const float* __restrict__ A,
                                                   const float* __restrict__ W,
                                                   int mode) {
    __shared__ unsigned sAh[2][64][12], sAl[2][64][12];   // half2 pairs, 8 used/row
    __shared__ unsigned sWh[2][8][136], sWl[2][8][136];   // [kpair][n], 128 used
    __shared__ float s_scale[D], s_shift[D];

    const int tid = threadIdx.x;
    const int rb = blockIdx.x * 64;
    const int lane = tid & 31, w = tid >> 5;
    const int rg = w & 3, cg = w >> 2;
    const int gi = lane >> 2, t4 = lane & 3;

    if (mode && tid < D) { s_scale[tid] = g_scale[tid]; s_shift[tid] = g_shift[tid]; }
    if (blockIdx.x == 0 && tid < D) { g_colsum[tid] = 0.0f; g_colsq[tid] = 0.0f; }
    __syncthreads();

    float c[8][4];
#pragma unroll
    for (int n0 = 0; n0 < 8; n0++)
#pragma unroll
        for (int j = 0; j < 4; j++) c[n0][j] = 0.0f;

    // staging roles
    const int a_row = tid >> 2;          // 0..63
    const int a_j = tid & 3;             // k-offset 4*a_j within slice
    const int grow = rb + a_row;
    const int w_kp = tid >> 5;           // k-pair 0..7
    const int w_n4 = (tid & 31) * 4;     // n 0..124
    const float* __restrict__ srcA = mode ? g_agg : A;

    float4 aReg, wReg0, wReg1;

    auto loadA = [&](int kk) {
        float4 a = make_float4(0.f, 0.f, 0.f, 0.f);
        if (grow < N_NODES) {
            a = *(const float4*)&srcA[grow * D + kk + a_j * 4];
            if (mode) {
                int cb = kk + a_j * 4;
                a.x = fmaxf(a.x * s_scale[cb + 0] + s_shift[cb + 0], 0.f);
                a.y = fmaxf(a.y * s_scale[cb + 1] + s_shift[cb + 1], 0.f);
                a.z = fmaxf(a.z * s_scale[cb + 2] + s_shift[cb + 2], 0.f);
                a.w = fmaxf(a.w * s_scale[cb + 3] + s_shift[cb + 3], 0.f);
            }
        }
        return a;
    };
    auto storeA = [&](int buf, float4 a) {
        __half hx = __float2half_rn(a.x), hy = __float2half_rn(a.y);
        __half hz = __float2half_rn(a.z), hw = __float2half_rn(a.w);
        unsigned hi0 = h2u(__halves2half2(hx, hy));
        unsigned hi1 = h2u(__halves2half2(hz, hw));
        unsigned lo0 = h2u(__floats2half2_rn(a.x - __half2float(hx),
                                             a.y - __half2float(hy)));
        unsigned lo1 = h2u(__floats2half2_rn(a.z - __half2float(hz),
                                             a.w - __half2float(hw)));
        sAh[buf][a_row][2 * a_j + 0] = hi0;
        sAh[buf][a_row][2 * a_j + 1] = hi1;
        sAl[buf][a_row][2 * a_j + 0] = lo0;
        sAl[buf][a_row][2 * a_j + 1] = lo1;
    };
    // wA = W[k_even][n4..n4+3], wB = W[k_odd][n4..n4+3] -> 4 half2 (n, kpair)
    auto storeW = [&](int buf, float4 wA, float4 wB) {
        float ea[4] = {wA.x, wA.y, wA.z, wA.w};
        float eb[4] = {wB.x, wB.y, wB.z, wB.w};
#pragma unroll
        for (int i = 0; i < 4; i++) {
            __half ha = __float2half_rn(ea[i]);
            __half hb = __float2half_rn(eb[i]);
            sWh[buf][w_kp][w_n4 + i] = h2u(__halves2half2(ha, hb));
            sWl[buf][w_kp][w_n4 + i] = h2u(__floats2half2_rn(
                ea[i] - __half2float(ha), eb[i] - __half2float(hb)));
        }
    };

    // prologue: slice 0
    aReg  = loadA(0);
    wReg0 = *(const float4*)&W[(2 * w_kp + 0) * D + w_n4];
    wReg1 = *(const float4*)&W[(2 * w_kp + 1) * D + w_n4];
    storeA(0, aReg);
    storeW(0, wReg0, wReg1);
    __syncthreads();

    for (int s = 0; s < 8; s++) {
        const int cur = s & 1;
        const int kk_next = (s + 1) * 16;

        if (s < 7) {
            aReg  = loadA(kk_next);
            wReg0 = *(const float4*)&W[(kk_next + 2 * w_kp + 0) * D + w_n4];
            wReg1 = *(const float4*)&W[(kk_next + 2 * w_kp + 1) * D + w_n4];
        }

        // ---- compute: one k16 step ----
        {
            const int r0 = rg * 16 + gi, r1 = r0 + 8;
            unsigned ah0 = sAh[cur][r0][t4],     ah1 = sAh[cur][r1][t4];
            unsigned ah2 = sAh[cur][r0][t4 + 4], ah3 = sAh[cur][r1][t4 + 4];
            unsigned al0 = sAl[cur][r0][t4],     al1 = sAl[cur][r1][t4];
            unsigned al2 = sAl[cur][r0][t4 + 4], al3 = sAl[cur][r1][t4 + 4];
#pragma unroll
            for (int n0 = 0; n0 < 8; n0++) {
                int nb = cg * 64 + n0 * 8 + gi;
                unsigned b0h = sWh[cur][t4][nb];
                unsigned b1h = sWh[cur][t4 + 4][nb];
                unsigned b0l = sWl[cur][t4][nb];
                unsigned b1l = sWl[cur][t4 + 4][nb];
                mma_f16(c[n0], ah0, ah1, ah2, ah3, b0h, b1h);   // hi*hi
                mma_f16(c[n0], ah0, ah1, ah2, ah3, b0l, b1l);   // hi*lo
                mma_f16(c[n0], al0, al1, al2, al3, b0h, b1h);   // lo*hi
            }
        }

        if (s < 7) {
            const int nxt = cur ^ 1;
            storeA(nxt, aReg);
            storeW(nxt, wReg0, wReg1);
            __syncthreads();
        }
    }

    // ---- epilogue: fp16 only (same as R15) ----
    const int row0 = rb + rg * 16 + gi;
    const int row1 = row0 + 8;
    const float di0 = (row0 < N_NODES) ? g_dinv[row0] : 0.0f;
    const float di1 = (row1 < N_NODES) ? g_dinv[row1] : 0.0f;
    __half2* hout = reinterpret_cast<__half2*>(g_hws_h);
#pragma unroll
    for (int n0 = 0; n0 < 8; n0++) {
        int n = cg * 64 + n0 * 8 + 2 * t4;
        int hc = n >> 1;
        if (row0 < N_NODES)
            hout[row0 * (D / 2) + hc] = __floats2half2_rn(c[n0][0] * di0, c[n0][1] * di0);
        if (row1 < N_NODES)
            hout[row1 * (D / 2) + hc] = __floats2half2_rn(c[n0][2] * di1, c[n0][3] * di1);
    }
}

// ---------------- aggregate (warp per node, fp16 gathers; R12 structure) ----
__global__ void aggregate_kernel(const float* __restrict__ b) {
    const int node = blockIdx.x * 8 + (threadIdx.x >> 5);
    const int lane = threadIdx.x & 31;
    if (node >= N_NODES) return;

    const int beg = g_rowstart[node];
    const int end = g_rowstart[node + 1];
    const uint2* __restrict__ hh = reinterpret_cast<const uint2*>(g_hws_h);

    float4 acc = make_float4(0.0f, 0.0f, 0.0f, 0.0f);
    for (int k0 = beg; k0 < end; k0 += 32) {
        int t = k0 + lane;
        int idx = (t < end) ? g_csr_src[t] : 0;
        int m = min(32, end - k0);
#pragma unroll 8
        for (int j = 0; j < m; j++) {
            int s = __shfl_sync(0xffffffffu, idx, j);
            uint2 raw = hh[s * 32 + lane];
            float2 f0 = __half22float2(*reinterpret_cast<__half2*>(&raw.x));
            float2 f1 = __half22float2(*reinterpret_cast<__half2*>(&raw.y));
            acc.x += f0.x; acc.y += f0.y; acc.z += f1.x; acc.w += f1.y;
        }
    }

    uint2 sraw = hh[node * 32 + lane];
    float2 s0 = __half22float2(*reinterpret_cast<__half2*>(&sraw.x));
    float2 s1 = __half22float2(*reinterpret_cast<__half2*>(&sraw.y));
    float dinv = g_dinv[node];
    float4 b4 = reinterpret_cast<const float4*>(b)[lane];
    float4 o;
    o.x = dinv * (acc.x + 2.0f * s0.x) + b4.x;
    o.y = dinv * (acc.y + 2.0f * s0.y) + b4.y;
    o.z = dinv * (acc.z + 2.0f * s1.x) + b4.z;
    o.w = dinv * (acc.w + 2.0f * s1.y) + b4.w;
    reinterpret_cast<float4*>(g_agg)[node * 32 + lane] = o;
}

// column sums/sumsq over g_agg; block handles 128 rows (thread = column)
__global__ void stats_kernel() {
    const int c = threadIdx.x;
    const int r0 = blockIdx.x * 128;
    float s = 0.0f, sq = 0.0f;
    for (int i = 0; i < 128; i++) {
        int r = r0 + i;
        if (r >= N_NODES) break;
        float v = g_agg[r * D + c];
        s += v;
        sq += v * v;
    }
    atomicAdd(&g_colsum[c], s);
    atomicAdd(&g_colsq[c], sq);
}

__global__ void bn_final_kernel(const float* __restrict__ gamma,
                                const float* __restrict__ beta) {
    int c = threadIdx.x;
    float mean = g_colsum[c] * (1.0f / (float)N_NODES);
    float var = g_colsq[c] * (1.0f / (float)N_NODES) - mean * mean;
    float sc = gamma[c] * rsqrtf(var + BN_EPS);
    g_scale[c] = sc;
    g_shift[c] = beta[c] - mean * sc;
}

// final layer only: out = relu(agg*scale + shift)
__global__ void apply_kernel(float* __restrict__ out) {
    int idx = blockIdx.x * blockDim.x + threadIdx.x;
    if (idx >= N_NODES * D) return;
    int c = idx & (D - 1);
    float v = g_agg[idx] * g_scale[c] + g_shift[c];
    out[idx] = fmaxf(v, 0.0f);
}

// ---------------- launch ----------------
extern "C" void kernel_launch(void* const* d_in, const int* in_sizes, int n_in,
                              void* d_out, int out_size) {
    const float* x = (const float*)d_in[0];
    const void* ei = d_in[1];
    const float* W[3]  = {(const float*)d_in[2],  (const float*)d_in[6],  (const float*)d_in[10]};
    const float* bb[3] = {(const float*)d_in[3],  (const float*)d_in[7],  (const float*)d_in[11]};
    const float* gg[3] = {(const float*)d_in[4],  (const float*)d_in[8],  (const float*)d_in[12]};
    const float* be[3] = {(const float*)d_in[5],  (const float*)d_in[9],  (const float*)d_in[13]};
    float* out = (float*)d_out;

    const int eblocks = (N_EDGES + 255) / 256;
    const int gemm_blocks = (N_NODES + 63) / 64;
    const int agg_blocks = (N_NODES + 7) / 8;
    const int stats_blocks = (N_NODES + 127) / 128;
    const int app_blocks = (N_NODES * D + 255) / 256;

    detect_kernel<<<NB, 256>>>((const int*)ei);                 // 1
    convert_count_kernel<<<eblocks, 256>>>(ei);                 // 2
    scanA_kernel<<<NB, 256>>>();                                // 3 (writes dinv)
    gemm_kernel<<<gemm_blocks, 256>>>(x, W[0], 0);              // 4 <- ncu slot
    scanB_kernel<<<1, 256>>>();                                 // 5
    scanC_kernel<<<NB, 256>>>();                                // 6
    fill_kernel<<<eblocks, 256>>>();                            // 7

    for (int layer = 0; layer < 3; layer++) {
        if (layer > 0)
            gemm_kernel<<<gemm_blocks, 256>>>(x, W[layer], 1);
        aggregate_kernel<<<agg_blocks, 256>>>(bb[layer]);
        stats_kernel<<<stats_blocks, 128>>>();
        bn_final_kernel<<<1, D>>>(gg[layer], be[layer]);
    }
    apply_kernel<<<app_blocks, 256>>>(out);
}